// round 2
// baseline (speedup 1.0000x reference)
#include <cuda_runtime.h>
#include <cuda_bf16.h>
#include <cstdint>

// Problem dims
#define NN     16384
#define NFEAT  512
#define NHID   256
#define NH2    64
#define NCLASS 10
#define CAP    128   // max nnz per adj row (mean 32, binomial tail negligible)

// ---------------- device scratch (no allocation allowed) ----------------
__device__ float    d_XW1[NN * NHID];     // x @ W1            16 MB
__device__ float    d_H1 [NN * NHID];     // relu(adj@XW1+b1)  16 MB
__device__ float    d_HW2[NN * NH2];      // H1 @ W2            4 MB
__device__ int      d_cols[NN * CAP];     // ELL col indices    8 MB
__device__ float    d_vals[NN * CAP];     // ELL values         8 MB
__device__ int      d_cnt [NN];
__device__ unsigned d_gmax[NH2];          // encoded col-max

// monotonic float<->uint mapping for atomicMax over signed floats
__device__ __forceinline__ unsigned enc_f(float f) {
    unsigned s = __float_as_uint(f);
    return (s & 0x80000000u) ? ~s : (s | 0x80000000u);
}
__device__ __forceinline__ float dec_f(unsigned k) {
    return __uint_as_float((k & 0x80000000u) ? (k & 0x7fffffffu) : ~k);
}

// ---------------- init ----------------
__global__ void init_gmax() {
    d_gmax[threadIdx.x] = 0u;  // smallest key under enc_f
}

// ---------------- dense SGEMM, register-blocked ----------------
template <int BM, int BN, int BK, int TM, int TN>
__global__ __launch_bounds__(256)
void sgemm(const float* __restrict__ A, const float* __restrict__ B,
           float* __restrict__ C, int M, int N, int K) {
    __shared__ float As[BK][BM];   // transposed A tile
    __shared__ float Bs[BK][BN];

    const int tid = threadIdx.x;
    constexpr int TCOLS = BN / TN;          // threads per row of micro-tiles
    const int trow = tid / TCOLS;
    const int tcol = tid % TCOLS;

    const float* Ab = A + (size_t)blockIdx.y * BM * K;
    const float* Bb = B + (size_t)blockIdx.x * BN;

    float acc[TM][TN];
    #pragma unroll
    for (int i = 0; i < TM; i++)
        #pragma unroll
        for (int j = 0; j < TN; j++) acc[i][j] = 0.f;

    // load mapping (256 threads, float4)
    constexpr int AK4 = BK / 4;             // float4 per A row
    constexpr int AROWSTR = 256 / AK4;      // rows covered per pass
    constexpr int AITERS = BM / AROWSTR;
    const int aRow  = tid / AK4;
    const int aCol4 = tid % AK4;

    constexpr int BN4 = BN / 4;
    constexpr int BROWSTR = 256 / BN4;
    constexpr int BITERS = BK / BROWSTR;
    const int bRow  = tid / BN4;
    const int bCol4 = tid % BN4;

    for (int k0 = 0; k0 < K; k0 += BK) {
        #pragma unroll
        for (int it = 0; it < AITERS; it++) {
            int r = aRow + it * AROWSTR;
            float4 v = *(const float4*)(Ab + (size_t)r * K + k0 + aCol4 * 4);
            As[aCol4 * 4 + 0][r] = v.x;
            As[aCol4 * 4 + 1][r] = v.y;
            As[aCol4 * 4 + 2][r] = v.z;
            As[aCol4 * 4 + 3][r] = v.w;
        }
        #pragma unroll
        for (int it = 0; it < BITERS; it++) {
            int r = bRow + it * BROWSTR;
            float4 v = *(const float4*)(Bb + (size_t)(k0 + r) * N + bCol4 * 4);
            *(float4*)&Bs[r][bCol4 * 4] = v;
        }
        __syncthreads();

        #pragma unroll
        for (int kk = 0; kk < BK; kk++) {
            float ra[TM], rb[TN];
            #pragma unroll
            for (int i = 0; i < TM; i++) ra[i] = As[kk][trow * TM + i];
            #pragma unroll
            for (int j = 0; j < TN; j++) rb[j] = Bs[kk][tcol * TN + j];
            #pragma unroll
            for (int i = 0; i < TM; i++)
                #pragma unroll
                for (int j = 0; j < TN; j++) acc[i][j] += ra[i] * rb[j];
        }
        __syncthreads();
    }

    float* Cb = C + (size_t)blockIdx.y * BM * N + blockIdx.x * BN;
    #pragma unroll
    for (int i = 0; i < TM; i++) {
        #pragma unroll
        for (int j = 0; j < TN; j += 4) {
            float4 v = make_float4(acc[i][j], acc[i][j + 1], acc[i][j + 2], acc[i][j + 3]);
            *(float4*)(Cb + (size_t)(trow * TM + i) * N + tcol * TN + j) = v;
        }
    }
}

// ---------------- adj sparsification: 1 block per row, streaming scan ----------------
__global__ __launch_bounds__(256)
void scan_adj(const float* __restrict__ adj) {
    const int row = blockIdx.x;
    __shared__ int scnt;
    if (threadIdx.x == 0) scnt = 0;
    __syncthreads();

    const float4* arow = (const float4*)(adj + (size_t)row * NN);
    const int base = row * CAP;
    #pragma unroll 4
    for (int i = threadIdx.x; i < NN / 4; i += 256) {
        float4 v = arow[i];
        if (v.x != 0.f) { int p = atomicAdd(&scnt, 1); if (p < CAP) { d_cols[base + p] = 4 * i + 0; d_vals[base + p] = v.x; } }
        if (v.y != 0.f) { int p = atomicAdd(&scnt, 1); if (p < CAP) { d_cols[base + p] = 4 * i + 1; d_vals[base + p] = v.y; } }
        if (v.z != 0.f) { int p = atomicAdd(&scnt, 1); if (p < CAP) { d_cols[base + p] = 4 * i + 2; d_vals[base + p] = v.z; } }
        if (v.w != 0.f) { int p = atomicAdd(&scnt, 1); if (p < CAP) { d_cols[base + p] = 4 * i + 3; d_vals[base + p] = v.w; } }
    }
    __syncthreads();
    if (threadIdx.x == 0) d_cnt[row] = min(scnt, CAP);
}

// ---------------- SpMM1: H1 = relu(adj @ XW1 + b1), one block per row, 256 cols ----------------
__global__ __launch_bounds__(256)
void spmm1(const float* __restrict__ b1) {
    const int row = blockIdx.x;
    const int c = threadIdx.x;
    const int n = d_cnt[row];

    __shared__ int   scol[CAP];
    __shared__ float sval[CAP];
    for (int i = threadIdx.x; i < n; i += 256) {
        scol[i] = d_cols[row * CAP + i];
        sval[i] = d_vals[row * CAP + i];
    }
    __syncthreads();

    float acc = b1[c];
    for (int i = 0; i < n; i++)
        acc += sval[i] * d_XW1[(size_t)scol[i] * NHID + c];
    d_H1[(size_t)row * NHID + c] = fmaxf(acc, 0.f);
}

// ---------------- SpMM2 + column max: h2 = adj @ HW2 + b2 ; g = colmax(h2) ----------------
__global__ __launch_bounds__(64)
void spmm2_max(const float* __restrict__ b2) {
    const int row = blockIdx.x;
    const int c = threadIdx.x;
    const int n = d_cnt[row];

    __shared__ int   scol[CAP];
    __shared__ float sval[CAP];
    for (int i = threadIdx.x; i < n; i += 64) {
        scol[i] = d_cols[row * CAP + i];
        sval[i] = d_vals[row * CAP + i];
    }
    __syncthreads();

    float acc = b2[c];
    for (int i = 0; i < n; i++)
        acc += sval[i] * d_HW2[(size_t)scol[i] * NH2 + c];
    atomicMax(&d_gmax[c], enc_f(acc));
}

// ---------------- tiny MLP head: one block ----------------
__global__ void head(const float* __restrict__ W3, const float* __restrict__ b3,
                     const float* __restrict__ W4, const float* __restrict__ b4,
                     const float* __restrict__ W5, const float* __restrict__ b5,
                     float* __restrict__ out) {
    __shared__ float g[NH2], g3[32], g4[16];
    const int t = threadIdx.x;
    g[t] = dec_f(d_gmax[t]);
    __syncthreads();
    if (t < 32) {
        float a = b3[t];
        #pragma unroll
        for (int k = 0; k < NH2; k++) a += g[k] * W3[k * 32 + t];
        g3[t] = fmaxf(a, 0.f);
    }
    __syncthreads();
    if (t < 16) {
        float a = b4[t];
        #pragma unroll
        for (int k = 0; k < 32; k++) a += g3[k] * W4[k * 16 + t];
        g4[t] = fmaxf(a, 0.f);
    }
    __syncthreads();
    if (t < NCLASS) {
        float a = b5[t];
        #pragma unroll
        for (int k = 0; k < 16; k++) a += g4[k] * W5[k * NCLASS + t];
        out[t] = a;
    }
}

// ---------------- launch: ONLY kernel launches, fully graph-capturable ----------------
extern "C" void kernel_launch(void* const* d_in, const int* in_sizes, int n_in,
                              void* d_out, int out_size) {
    const float* x   = (const float*)d_in[0];
    const float* adj = (const float*)d_in[1];
    const float* W1  = (const float*)d_in[2];
    const float* b1  = (const float*)d_in[3];
    const float* W2  = (const float*)d_in[4];
    const float* b2  = (const float*)d_in[5];
    const float* W3  = (const float*)d_in[6];
    const float* b3  = (const float*)d_in[7];
    const float* W4  = (const float*)d_in[8];
    const float* b4  = (const float*)d_in[9];
    const float* W5  = (const float*)d_in[10];
    const float* b5  = (const float*)d_in[11];
    float* out = (float*)d_out;

    init_gmax<<<1, NH2>>>();

    // XW1 = x @ W1   [16384,512]@[512,256]
    float* xw1;  // device-global destinations are referenced inside kernels;
    // sgemm stays generic, so pass the globals via their device addresses
    // obtained at compile time through a small launcher trick: use separate
    // wrapper kernels? Simpler: sgemm writes through pointer params that we
    // get from device symbols — but to stay capture-pure we instead pass
    // the __device__ arrays directly (valid: device symbols decay to
    // addresses usable in device code only). So use dedicated wrappers below.
    (void)xw1;

    // Dedicated launches using device-global scratch via helper kernels:
    extern __global__ void sgemm1_entry(const float*, const float*);
    extern __global__ void sgemm2_entry(const float*);

    sgemm1_entry<<<dim3(NHID / 128, NN / 128), 256>>>(x, W1);
    scan_adj<<<NN, 256>>>(adj);
    spmm1<<<NN, 256>>>(b1);
    sgemm2_entry<<<dim3(NH2 / 64, NN / 64), 256>>>(W2);
    spmm2_max<<<NN, 64>>>(b2);
    head<<<1, NH2>>>(W3, b3, W4, b4, W5, b5, out);
}

// ---------------- wrappers binding device-global scratch to sgemm ----------------
template <int BM, int BN, int BK, int TM, int TN>
__device__ __forceinline__
void sgemm_body(const float* __restrict__ A, const float* __restrict__ B,
                float* __restrict__ C, int M, int N, int K);

// Re-implement as device-callable body via the same code path: simplest is to
// duplicate the launch through the template kernel with pointers to globals.
__global__ __launch_bounds__(256)
void sgemm1_entry(const float* __restrict__ x, const float* __restrict__ W1v) {
    // delegate: identical body to sgemm<128,128,16,8,8> with C = d_XW1
    __shared__ float As[16][128];
    __shared__ float Bs[16][128];
    const int tid = threadIdx.x;
    const int trow = tid / 16;          // TCOLS = 128/8 = 16
    const int tcol = tid % 16;
    const float* Ab = x + (size_t)blockIdx.y * 128 * NFEAT;
    const float* Bb = W1v + (size_t)blockIdx.x * 128;

    float acc[8][8];
    #pragma unroll
    for (int i = 0; i < 8; i++)
        #pragma unroll
        for (int j = 0; j < 8; j++) acc[i][j] = 0.f;

    const int aRow  = tid / 4;   // AK4 = 4
    const int aCol4 = tid % 4;
    const int bRow  = tid / 32;  // BN4 = 32
    const int bCol4 = tid % 32;

    for (int k0 = 0; k0 < NFEAT; k0 += 16) {
        #pragma unroll
        for (int it = 0; it < 2; it++) {           // AITERS = 128/64
            int r = aRow + it * 64;
            float4 v = *(const float4*)(Ab + (size_t)r * NFEAT + k0 + aCol4 * 4);
            As[aCol4 * 4 + 0][r] = v.x;
            As[aCol4 * 4 + 1][r] = v.y;
            As[aCol4 * 4 + 2][r] = v.z;
            As[aCol4 * 4 + 3][r] = v.w;
        }
        #pragma unroll
        for (int it = 0; it < 2; it++) {           // BITERS = 16/8
            int r = bRow + it * 8;
            float4 v = *(const float4*)(Bb + (size_t)(k0 + r) * NHID + bCol4 * 4);
            *(float4*)&Bs[r][bCol4 * 4] = v;
        }
        __syncthreads();
        #pragma unroll
        for (int kk = 0; kk < 16; kk++) {
            float ra[8], rb[8];
            #pragma unroll
            for (int i = 0; i < 8; i++) ra[i] = As[kk][trow * 8 + i];
            #pragma unroll
            for (int j = 0; j < 8; j++) rb[j] = Bs[kk][tcol * 8 + j];
            #pragma unroll
            for (int i = 0; i < 8; i++)
                #pragma unroll
                for (int j = 0; j < 8; j++) acc[i][j] += ra[i] * rb[j];
        }
        __syncthreads();
    }

    float* Cb = d_XW1 + (size_t)blockIdx.y * 128 * NHID + blockIdx.x * 128;
    #pragma unroll
    for (int i = 0; i < 8; i++)
        #pragma unroll
        for (int j = 0; j < 8; j += 4) {
            float4 v = make_float4(acc[i][j], acc[i][j+1], acc[i][j+2], acc[i][j+3]);
            *(float4*)(Cb + (size_t)(trow * 8 + i) * NHID + tcol * 8 + j) = v;
        }
}

__global__ __launch_bounds__(256)
void sgemm2_entry(const float* __restrict__ W2v) {
    // HW2 = H1 @ W2: [16384,256]@[256,64], BM=64,BN=64,BK=16,TM=4,TN=4
    __shared__ float As[16][64];
    __shared__ float Bs[16][64];
    const int tid = threadIdx.x;
    const int trow = tid / 16;          // TCOLS = 64/4 = 16
    const int tcol = tid % 16;
    const float* Ab = d_H1 + (size_t)blockIdx.y * 64 * NHID;
    const float* Bb = W2v + (size_t)blockIdx.x * 64;

    float acc[4][4];
    #pragma unroll
    for (int i = 0; i < 4; i++)
        #pragma unroll
        for (int j = 0; j < 4; j++) acc[i][j] = 0.f;

    const int aRow  = tid / 4;   // AK4 = 4
    const int aCol4 = tid % 4;
    const int bRow  = tid / 16;  // BN4 = 16
    const int bCol4 = tid % 16;

    for (int k0 = 0; k0 < NHID; k0 += 16) {
        // A: 64 rows x 16 cols; 256 threads cover 64 rows in one pass
        {
            int r = aRow;
            float4 v = *(const float4*)(Ab + (size_t)r * NHID + k0 + aCol4 * 4);
            As[aCol4 * 4 + 0][r] = v.x;
            As[aCol4 * 4 + 1][r] = v.y;
            As[aCol4 * 4 + 2][r] = v.z;
            As[aCol4 * 4 + 3][r] = v.w;
        }
        // B: 16 rows x 64 cols = 16 float4/row * 16 rows = 256 float4
        {
            int r = bRow;
            float4 v = *(const float4*)(Bb + (size_t)(k0 + r) * NH2 + bCol4 * 4);
            *(float4*)&Bs[r][bCol4 * 4] = v;
        }
        __syncthreads();
        #pragma unroll
        for (int kk = 0; kk < 16; kk++) {
            float ra[4], rb[4];
            #pragma unroll
            for (int i = 0; i < 4; i++) ra[i] = As[kk][trow * 4 + i];
            #pragma unroll
            for (int j = 0; j < 4; j++) rb[j] = Bs[kk][tcol * 4 + j];
            #pragma unroll
            for (int i = 0; i < 4; i++)
                #pragma unroll
                for (int j = 0; j < 4; j++) acc[i][j] += ra[i] * rb[j];
        }
        __syncthreads();
    }

    float* Cb = d_HW2 + (size_t)blockIdx.y * 64 * NH2 + blockIdx.x * 64;
    #pragma unroll
    for (int i = 0; i < 4; i++)
        #pragma unroll
        for (int j = 0; j < 4; j += 4) {
            float4 v = make_float4(acc[i][j], acc[i][j+1], acc[i][j+2], acc[i][j+3]);
            *(float4*)(Cb + (size_t)(trow * 4 + i) * NH2 + tcol * 4 + j) = v;
        }
}

// round 4
// speedup vs baseline: 1.0868x; 1.0868x over previous
#include <cuda_runtime.h>
#include <cuda_bf16.h>
#include <cstdint>

// Problem dims
#define NN     16384
#define NFEAT  512
#define NHID   256
#define NH2    64
#define NCLASS 10
#define CAP    128   // max nnz per adj row (mean 32, binomial tail negligible)

#define GEMM1_BLOCKS 256          // (NHID/128) * (NN/128) = 2*128
#define FUSED_GRID   (GEMM1_BLOCKS + NN)

// ---------------- device scratch (no allocation allowed) ----------------
__device__ float    d_XW1[NN * NHID];     // x @ W1            16 MB
__device__ float    d_H1 [NN * NHID];     // relu(adj@XW1+b1)  16 MB
__device__ float    d_HW2[NN * NH2];      // H1 @ W2            4 MB
__device__ int      d_cols[NN * CAP];     // ELL col indices    8 MB
__device__ float    d_vals[NN * CAP];     // ELL values         8 MB
__device__ int      d_cnt [NN];
__device__ unsigned d_gmax[NH2];          // encoded col-max

// monotonic float<->uint mapping for atomicMax over signed floats
__device__ __forceinline__ unsigned enc_f(float f) {
    unsigned s = __float_as_uint(f);
    return (s & 0x80000000u) ? ~s : (s | 0x80000000u);
}
__device__ __forceinline__ float dec_f(unsigned k) {
    return __uint_as_float((k & 0x80000000u) ? (k & 0x7fffffffu) : ~k);
}

// ---------------- init ----------------
__global__ void init_gmax() {
    d_gmax[threadIdx.x] = 0u;  // smallest key under enc_f
}

// ---------------- FUSED: sgemm1 (blocks 0..255) + adj scan (blocks 256..) ----
// These two phases are data-independent: sgemm1 is FFMA-pipe-bound, the scan
// is pure DRAM streaming. Co-residency overlaps the two rooflines.
__global__ __launch_bounds__(256)
void fused_gemm1_scan(const float* __restrict__ x, const float* __restrict__ W1v,
                      const float* __restrict__ adj) {
    if (blockIdx.x < GEMM1_BLOCKS) {
        // ---- sgemm1: XW1 = x @ W1, BM=BN=128, BK=16, TM=TN=8 ----
        __shared__ float As[16][128];
        __shared__ float Bs[16][128];
        const int tid = threadIdx.x;
        const int trow = tid / 16;
        const int tcol = tid % 16;
        const int bx = blockIdx.x % 2;       // NHID/128 = 2
        const int by = blockIdx.x / 2;
        const float* Ab = x + (size_t)by * 128 * NFEAT;
        const float* Bb = W1v + (size_t)bx * 128;

        float acc[8][8];
        #pragma unroll
        for (int i = 0; i < 8; i++)
            #pragma unroll
            for (int j = 0; j < 8; j++) acc[i][j] = 0.f;

        const int aRow  = tid / 4;   // 4 float4 per A row (BK=16)
        const int aCol4 = tid % 4;
        const int bRow  = tid / 32;  // 32 float4 per B row (BN=128)
        const int bCol4 = tid % 32;

        for (int k0 = 0; k0 < NFEAT; k0 += 16) {
            #pragma unroll
            for (int it = 0; it < 2; it++) {
                int r = aRow + it * 64;
                float4 v = *(const float4*)(Ab + (size_t)r * NFEAT + k0 + aCol4 * 4);
                As[aCol4 * 4 + 0][r] = v.x;
                As[aCol4 * 4 + 1][r] = v.y;
                As[aCol4 * 4 + 2][r] = v.z;
                As[aCol4 * 4 + 3][r] = v.w;
            }
            #pragma unroll
            for (int it = 0; it < 2; it++) {
                int r = bRow + it * 8;
                float4 v = *(const float4*)(Bb + (size_t)(k0 + r) * NHID + bCol4 * 4);
                *(float4*)&Bs[r][bCol4 * 4] = v;
            }
            __syncthreads();
            #pragma unroll
            for (int kk = 0; kk < 16; kk++) {
                float ra[8], rb[8];
                #pragma unroll
                for (int i = 0; i < 8; i++) ra[i] = As[kk][trow * 8 + i];
                #pragma unroll
                for (int j = 0; j < 8; j++) rb[j] = Bs[kk][tcol * 8 + j];
                #pragma unroll
                for (int i = 0; i < 8; i++)
                    #pragma unroll
                    for (int j = 0; j < 8; j++) acc[i][j] += ra[i] * rb[j];
            }
            __syncthreads();
        }

        float* Cb = d_XW1 + (size_t)by * 128 * NHID + bx * 128;
        #pragma unroll
        for (int i = 0; i < 8; i++)
            #pragma unroll
            for (int j = 0; j < 8; j += 4) {
                float4 v = make_float4(acc[i][j], acc[i][j+1], acc[i][j+2], acc[i][j+3]);
                *(float4*)(Cb + (size_t)(trow * 8 + i) * NHID + tcol * 8 + j) = v;
            }
    } else {
        // ---- adj sparsification: one block per adj row ----
        const int row = blockIdx.x - GEMM1_BLOCKS;
        __shared__ int scnt;
        if (threadIdx.x == 0) scnt = 0;
        __syncthreads();

        const float4* arow = (const float4*)(adj + (size_t)row * NN);
        const int base = row * CAP;
        #pragma unroll 8
        for (int i = threadIdx.x; i < NN / 4; i += 256) {
            float4 v = arow[i];
            if (v.x != 0.f) { int p = atomicAdd(&scnt, 1); if (p < CAP) { d_cols[base + p] = 4 * i + 0; d_vals[base + p] = v.x; } }
            if (v.y != 0.f) { int p = atomicAdd(&scnt, 1); if (p < CAP) { d_cols[base + p] = 4 * i + 1; d_vals[base + p] = v.y; } }
            if (v.z != 0.f) { int p = atomicAdd(&scnt, 1); if (p < CAP) { d_cols[base + p] = 4 * i + 2; d_vals[base + p] = v.z; } }
            if (v.w != 0.f) { int p = atomicAdd(&scnt, 1); if (p < CAP) { d_cols[base + p] = 4 * i + 3; d_vals[base + p] = v.w; } }
        }
        __syncthreads();
        if (threadIdx.x == 0) d_cnt[row] = min(scnt, CAP);
    }
}

// ---------------- SpMM1: H1 = relu(adj @ XW1 + b1) ----------------
// 4 rows per block; 64 lanes x float4 cover NHID=256 columns.
__global__ __launch_bounds__(256)
void spmm1(const float* __restrict__ b1) {
    const int r    = threadIdx.x >> 6;     // 0..3
    const int lane = threadIdx.x & 63;     // 0..63
    const int row  = blockIdx.x * 4 + r;

    __shared__ int   soff[4][CAP];         // premultiplied col*NHID
    __shared__ float sval[4][CAP];
    const int n = d_cnt[row];
    for (int i = lane; i < n; i += 64) {
        soff[r][i] = d_cols[row * CAP + i] * NHID;
        sval[r][i] = d_vals[row * CAP + i];
    }
    __syncthreads();

    float4 acc = *(const float4*)(b1 + lane * 4);
    int i = 0;
    for (; i + 2 <= n; i += 2) {
        const float4 v0 = *(const float4*)(d_XW1 + soff[r][i]     + lane * 4);
        const float4 v1 = *(const float4*)(d_XW1 + soff[r][i + 1] + lane * 4);
        const float s0 = sval[r][i], s1 = sval[r][i + 1];
        acc.x += s0 * v0.x; acc.y += s0 * v0.y; acc.z += s0 * v0.z; acc.w += s0 * v0.w;
        acc.x += s1 * v1.x; acc.y += s1 * v1.y; acc.z += s1 * v1.z; acc.w += s1 * v1.w;
    }
    if (i < n) {
        const float4 v = *(const float4*)(d_XW1 + soff[r][i] + lane * 4);
        const float s = sval[r][i];
        acc.x += s * v.x; acc.y += s * v.y; acc.z += s * v.z; acc.w += s * v.w;
    }
    acc.x = fmaxf(acc.x, 0.f); acc.y = fmaxf(acc.y, 0.f);
    acc.z = fmaxf(acc.z, 0.f); acc.w = fmaxf(acc.w, 0.f);
    *(float4*)(d_H1 + (size_t)row * NHID + lane * 4) = acc;
}

// ---------------- sgemm2: HW2 = H1 @ W2  [16384,256]@[256,64] ----------------
__global__ __launch_bounds__(256)
void sgemm2_entry(const float* __restrict__ W2v) {
    __shared__ float As[16][64];
    __shared__ float Bs[16][64];
    const int tid = threadIdx.x;
    const int trow = tid / 16;
    const int tcol = tid % 16;
    const float* Ab = d_H1 + (size_t)blockIdx.y * 64 * NHID;
    const float* Bb = W2v + (size_t)blockIdx.x * 64;

    float acc[4][4];
    #pragma unroll
    for (int i = 0; i < 4; i++)
        #pragma unroll
        for (int j = 0; j < 4; j++) acc[i][j] = 0.f;

    const int aRow  = tid / 4;
    const int aCol4 = tid % 4;
    const int bRow  = tid / 16;
    const int bCol4 = tid % 16;

    for (int k0 = 0; k0 < NHID; k0 += 16) {
        {
            float4 v = *(const float4*)(Ab + (size_t)aRow * NHID + k0 + aCol4 * 4);
            As[aCol4 * 4 + 0][aRow] = v.x;
            As[aCol4 * 4 + 1][aRow] = v.y;
            As[aCol4 * 4 + 2][aRow] = v.z;
            As[aCol4 * 4 + 3][aRow] = v.w;
        }
        {
            float4 v = *(const float4*)(Bb + (size_t)(k0 + bRow) * NH2 + bCol4 * 4);
            *(float4*)&Bs[bRow][bCol4 * 4] = v;
        }
        __syncthreads();
        #pragma unroll
        for (int kk = 0; kk < 16; kk++) {
            float ra[4], rb[4];
            #pragma unroll
            for (int i = 0; i < 4; i++) ra[i] = As[kk][trow * 4 + i];
            #pragma unroll
            for (int j = 0; j < 4; j++) rb[j] = Bs[kk][tcol * 4 + j];
            #pragma unroll
            for (int i = 0; i < 4; i++)
                #pragma unroll
                for (int j = 0; j < 4; j++) acc[i][j] += ra[i] * rb[j];
        }
        __syncthreads();
    }

    float* Cb = d_HW2 + (size_t)blockIdx.y * 64 * NH2 + blockIdx.x * 64;
    #pragma unroll
    for (int i = 0; i < 4; i++) {
        float4 v = make_float4(acc[i][0], acc[i][1], acc[i][2], acc[i][3]);
        *(float4*)(Cb + (size_t)(trow * 4 + i) * NH2 + tcol * 4) = v;
    }
}

// ---------------- SpMM2 + col-max: g = colmax(adj @ HW2 + b2) ----------------
// 16 rows per block; 16 lanes x float4 cover NH2=64 columns.
// Block-local max reduction -> 64 atomics per block (1024 blocks).
__global__ __launch_bounds__(256)
void spmm2_max(const float* __restrict__ b2) {
    const int r    = threadIdx.x >> 4;     // 0..15
    const int lane = threadIdx.x & 15;     // 0..15
    const int row  = blockIdx.x * 16 + r;

    __shared__ int   soff[16][CAP];
    __shared__ float sval[16][CAP];
    const int n = d_cnt[row];
    for (int i = lane; i < n; i += 16) {
        soff[r][i] = d_cols[row * CAP + i] * NH2;
        sval[r][i] = d_vals[row * CAP + i];
    }
    __syncthreads();

    float4 acc = *(const float4*)(b2 + lane * 4);
    int i = 0;
    for (; i + 2 <= n; i += 2) {
        const float4 v0 = *(const float4*)(d_HW2 + soff[r][i]     + lane * 4);
        const float4 v1 = *(const float4*)(d_HW2 + soff[r][i + 1] + lane * 4);
        const float s0 = sval[r][i], s1 = sval[r][i + 1];
        acc.x += s0 * v0.x; acc.y += s0 * v0.y; acc.z += s0 * v0.z; acc.w += s0 * v0.w;
        acc.x += s1 * v1.x; acc.y += s1 * v1.y; acc.z += s1 * v1.z; acc.w += s1 * v1.w;
    }
    if (i < n) {
        const float4 v = *(const float4*)(d_HW2 + soff[r][i] + lane * 4);
        const float s = sval[r][i];
        acc.x += s * v.x; acc.y += s * v.y; acc.z += s * v.z; acc.w += s * v.w;
    }
    __syncthreads();  // reuse smem
    __shared__ float4 smax[16][16];
    smax[r][lane] = acc;
    __syncthreads();
    if (r == 0) {
        float4 m = smax[0][lane];
        #pragma unroll
        for (int k = 1; k < 16; k++) {
            float4 v = smax[k][lane];
            m.x = fmaxf(m.x, v.x); m.y = fmaxf(m.y, v.y);
            m.z = fmaxf(m.z, v.z); m.w = fmaxf(m.w, v.w);
        }
        atomicMax(&d_gmax[lane * 4 + 0], enc_f(m.x));
        atomicMax(&d_gmax[lane * 4 + 1], enc_f(m.y));
        atomicMax(&d_gmax[lane * 4 + 2], enc_f(m.z));
        atomicMax(&d_gmax[lane * 4 + 3], enc_f(m.w));
    }
}

// ---------------- tiny MLP head: one block ----------------
__global__ void head(const float* __restrict__ W3, const float* __restrict__ b3,
                     const float* __restrict__ W4, const float* __restrict__ b4,
                     const float* __restrict__ W5, const float* __restrict__ b5,
                     float* __restrict__ out) {
    __shared__ float g[NH2], g3[32], g4[16];
    const int t = threadIdx.x;
    g[t] = dec_f(d_gmax[t]);
    __syncthreads();
    if (t < 32) {
        float a = b3[t];
        #pragma unroll
        for (int k = 0; k < NH2; k++) a += g[k] * W3[k * 32 + t];
        g3[t] = fmaxf(a, 0.f);
    }
    __syncthreads();
    if (t < 16) {
        float a = b4[t];
        #pragma unroll
        for (int k = 0; k < 32; k++) a += g3[k] * W4[k * 16 + t];
        g4[t] = fmaxf(a, 0.f);
    }
    __syncthreads();
    if (t < NCLASS) {
        float a = b5[t];
        #pragma unroll
        for (int k = 0; k < 16; k++) a += g4[k] * W5[k * NCLASS + t];
        out[t] = a;
    }
}

// ---------------- launch: ONLY kernel launches, fully graph-capturable ----------------
extern "C" void kernel_launch(void* const* d_in, const int* in_sizes, int n_in,
                              void* d_out, int out_size) {
    const float* x   = (const float*)d_in[0];
    const float* adj = (const float*)d_in[1];
    const float* W1  = (const float*)d_in[2];
    const float* b1  = (const float*)d_in[3];
    const float* W2  = (const float*)d_in[4];
    const float* b2  = (const float*)d_in[5];
    const float* W3  = (const float*)d_in[6];
    const float* b3  = (const float*)d_in[7];
    const float* W4  = (const float*)d_in[8];
    const float* b4  = (const float*)d_in[9];
    const float* W5  = (const float*)d_in[10];
    const float* b5  = (const float*)d_in[11];
    float* out = (float*)d_out;

    init_gmax<<<1, NH2>>>();
    fused_gemm1_scan<<<FUSED_GRID, 256>>>(x, W1, adj);
    spmm1<<<NN / 4, 256>>>(b1);
    sgemm2_entry<<<dim3(NH2 / 64, NN / 64), 256>>>(W2);
    spmm2_max<<<NN / 16, 256>>>(b2);
    head<<<1, NH2>>>(W3, b3, W4, b4, W5, b5, out);
}